// round 16
// baseline (speedup 1.0000x reference)
#include <cuda_runtime.h>

// Problem dims
#define BATCH 512
#define LSEQ  256     // H*W = 16*16
#define CIN   32
#define HID   128
#define OUTD  512

// ---------------- scratch (static device globals; no runtime allocation) ---
__device__ float d_Wc[HID * CIN];                       // folded W_ih @ W_in  (128x32)
__device__ float d_bc[HID];                             // folded bias (incl. b_hh)
__device__ float d_pooled[BATCH * HID];

// ---------------- f32x2 helpers (Blackwell packed fp32 FMA) ----------------
__device__ __forceinline__ unsigned long long pack2(float a, float b) {
    unsigned long long r;
    asm("mov.b64 %0, {%1, %2};" : "=l"(r) : "f"(a), "f"(b));
    return r;
}
__device__ __forceinline__ void unpack2(unsigned long long v, float& a, float& b) {
    asm("mov.b64 {%0, %1}, %2;" : "=f"(a), "=f"(b) : "l"(v));
}
__device__ __forceinline__ void ffma2(unsigned long long& acc,
                                      unsigned long long a, unsigned long long b) {
    asm("fma.rn.f32x2 %0, %1, %2, %0;" : "+l"(acc) : "l"(a), "l"(b));
}

// ---------------------------------------------------------------------------
// Kernel A: fold the two input linears + b_hh.
// ---------------------------------------------------------------------------
__global__ void combine_kernel(const float* __restrict__ W_in,
                               const float* __restrict__ b_in,
                               const float* __restrict__ W_ih,
                               const float* __restrict__ b_ih,
                               const float* __restrict__ b_hh) {
    int idx = blockIdx.x * blockDim.x + threadIdx.x;
    if (idx < HID * CIN) {
        int j = idx >> 5, c = idx & 31;
        float s = 0.f;
        #pragma unroll 8
        for (int m = 0; m < 64; m++) s += W_ih[j * 64 + m] * W_in[m * 32 + c];
        d_Wc[idx] = s;
    }
    if (idx < HID) {
        float s = b_ih[idx] + b_hh[idx];
        #pragma unroll 8
        for (int m = 0; m < 64; m++) s += W_ih[idx * 64 + m] * b_in[m];
        d_bc[idx] = s;
    }
}

// ---------------------------------------------------------------------------
// Kernel C: fully fused input-projection + RNN scan + upsample/hardswish/pool.
//   h_t = tanh( Wc @ x[:, :, t] + bc + W_hh @ h_{t-1} );  pooled = mean of
//   hardswish(bilinear_upsample_2x(h reshaped 16x16)) accumulated in-kernel.
// 256 CTAs x 2 batch rows, 128 threads, 2 CTAs/SM (dynamic smem 84.5KB/CTA).
// tid = jg*8 + kc. Per-step work identical to the R11/R14 optimum
// (10 LDS.128, 160 ffma2, 14 shuffles, 1 barrier). The h time-series for this
// thread's j is kept in a rolling 2-grid-row history (thread-private smem,
// layout [slot][x][tid] -> conflict-free, no extra syncs); every 16 steps a
// small pooling burst (1-3 output rows) fills the idle issue slots. d_hs and
// pool_kernel are DELETED (−26us launch, −128MB DRAM round trip).
// ---------------------------------------------------------------------------
__global__ void __launch_bounds__(128, 2) rnn_kernel(const float* __restrict__ x,
                                                     const float* __restrict__ h0,
                                                     const float* __restrict__ W_hh) {
    extern __shared__ __align__(16) float dyn[];
    float* hist = dyn;                    // [(r*2+ypar)*16 + gx][128]  (64KB)
    float* hsmp = dyn + 16384;            // 2 bufs x 320 floats
    float* xsmp = dyn + 16384 + 640;      // [buf][row][tt][c] 2*2*16*32

    int tid = threadIdx.x;
    int kc = tid & 7;           // 0..7
    int jg = tid >> 3;          // 0..15
    int r0 = blockIdx.x * 2;

    // W_hh slices: 8 j rows x 16 k as pairs (64 ull = 128 regs)
    unsigned long long wp[8][8];
    #pragma unroll
    for (int jj = 0; jj < 8; jj++) {
        const float* wrow = W_hh + (jj * 16 + jg) * 128 + kc * 16;
        #pragma unroll
        for (int i = 0; i < 4; i++) {
            float4 w = *(const float4*)(wrow + i * 4);
            wp[jj][2 * i]     = pack2(w.x, w.y);
            wp[jj][2 * i + 1] = pack2(w.z, w.w);
        }
    }
    // Wc slices: 8 j rows x 4 c as pairs (16 ull = 32 regs)
    unsigned long long wc[8][2];
    #pragma unroll
    for (int jj = 0; jj < 8; jj++) {
        float4 w = *(const float4*)&d_Wc[(jj * 16 + jg) * 32 + kc * 4];
        wc[jj][0] = pack2(w.x, w.y);
        wc[jj][1] = pack2(w.z, w.w);
    }
    int j_out = kc * 16 + jg;
    float bcj = d_bc[j_out];

    // init h state from h0
    for (int i = tid; i < 256; i += 128) {
        int r = i >> 7, k = i & 127;
        hsmp[r * 160 + (k >> 4) * 20 + (k & 15)] = h0[(r0 + r) * 128 + k];
    }

    // x tile loader: thread (xr, xhalf, xc) loads x[b_r][c][t0+half*8 ..+8)
    int xr = tid >> 6, xhalf = (tid >> 5) & 1, xc = tid & 31;
    const float* xbase = x + ((size_t)(r0 + xr) * 32 + xc) * 256 + xhalf * 8;
    {
        float4 v0 = *(const float4*)(xbase);
        float4 v1 = *(const float4*)(xbase + 4);
        float* xd = &xsmp[((0 * 2 + xr) * 16 + xhalf * 8) * 32 + xc];
        xd[0 * 32] = v0.x; xd[1 * 32] = v0.y; xd[2 * 32] = v0.z; xd[3 * 32] = v0.w;
        xd[4 * 32] = v1.x; xd[5 * 32] = v1.y; xd[6 * 32] = v1.z; xd[7 * 32] = v1.w;
    }
    __syncthreads();

    int hoff = kc * 20;                    // this thread's k-chunk base (words)
    int sst = kc * 20 + jg;                // STS slot (chunk kc, offset jg)

    bool b0 = (kc & 1), b1 = (kc & 2), b2 = (kc & 4);
    float accA = 0.f, accB = 0.f;          // pooled accumulators

    for (int t = 0; t < 256; t++) {
        int tt = t & 15;
        int e = t >> 4;

        // prefetch next x epoch (buffer last touched 16 steps ago)
        if (tt == 0 && (t + 16) < 256) {
            int t0 = t + 16;
            float4 v0 = *(const float4*)(xbase + t0);
            float4 v1 = *(const float4*)(xbase + t0 + 4);
            float* xd = &xsmp[((((e + 1) & 1) * 2 + xr) * 16 + xhalf * 8) * 32 + xc];
            xd[0 * 32] = v0.x; xd[1 * 32] = v0.y; xd[2 * 32] = v0.z; xd[3 * 32] = v0.w;
            xd[4 * 32] = v1.x; xd[5 * 32] = v1.y; xd[6 * 32] = v1.z; xd[7 * 32] = v1.w;
        }

        const float* rbuf = hsmp + (t & 1) * 320;
        float* wbuf = hsmp + ((t + 1) & 1) * 320;

        // ---- per-(row,jj) partials over this thread's 16-k chunk + 4-c proj
        float pr[2][8];
        {
            const ulonglong2* hb = (const ulonglong2*)(rbuf + hoff);
            ulonglong2 hv0 = hb[0], hv1 = hb[1], hv2 = hb[2], hv3 = hb[3];
            ulonglong2 xv = *(const ulonglong2*)&xsmp[(((e & 1) * 2 + 0) * 16 + tt) * 32 + kc * 4];
            #pragma unroll
            for (int jj = 0; jj < 8; jj++) {
                unsigned long long a = 0ull;
                ffma2(a, wp[jj][0], hv0.x);
                ffma2(a, wp[jj][1], hv0.y);
                ffma2(a, wp[jj][2], hv1.x);
                ffma2(a, wp[jj][3], hv1.y);
                ffma2(a, wp[jj][4], hv2.x);
                ffma2(a, wp[jj][5], hv2.y);
                ffma2(a, wp[jj][6], hv3.x);
                ffma2(a, wp[jj][7], hv3.y);
                ffma2(a, wc[jj][0], xv.x);
                ffma2(a, wc[jj][1], xv.y);
                float lo, hi; unpack2(a, lo, hi);
                pr[0][jj] = lo + hi;
            }
        }
        {
            const ulonglong2* hb = (const ulonglong2*)(rbuf + 160 + hoff);
            ulonglong2 hv0 = hb[0], hv1 = hb[1], hv2 = hb[2], hv3 = hb[3];
            ulonglong2 xv = *(const ulonglong2*)&xsmp[(((e & 1) * 2 + 1) * 16 + tt) * 32 + kc * 4];
            #pragma unroll
            for (int jj = 0; jj < 8; jj++) {
                unsigned long long a = 0ull;
                ffma2(a, wp[jj][0], hv0.x);
                ffma2(a, wp[jj][1], hv0.y);
                ffma2(a, wp[jj][2], hv1.x);
                ffma2(a, wp[jj][3], hv1.y);
                ffma2(a, wp[jj][4], hv2.x);
                ffma2(a, wp[jj][5], hv2.y);
                ffma2(a, wp[jj][6], hv3.x);
                ffma2(a, wp[jj][7], hv3.y);
                ffma2(a, wc[jj][0], xv.x);
                ffma2(a, wc[jj][1], xv.y);
                float lo, hi; unpack2(a, lo, hi);
                pr[1][jj] = lo + hi;
            }
        }

        // ---- 3-level reduce-scatter over the 8 kc lanes ----
        float q[2][4], u[2][2], f[2];
        #pragma unroll
        for (int r = 0; r < 2; r++) {
            #pragma unroll
            for (int m = 0; m < 4; m++)
                q[r][m] = (b0 ? pr[r][2 * m + 1] : pr[r][2 * m])
                        + __shfl_xor_sync(~0u, b0 ? pr[r][2 * m] : pr[r][2 * m + 1], 1);
        }
        #pragma unroll
        for (int r = 0; r < 2; r++) {
            #pragma unroll
            for (int m = 0; m < 2; m++)
                u[r][m] = (b1 ? q[r][2 * m + 1] : q[r][2 * m])
                        + __shfl_xor_sync(~0u, b1 ? q[r][2 * m] : q[r][2 * m + 1], 2);
        }
        #pragma unroll
        for (int r = 0; r < 2; r++)
            f[r] = (b2 ? u[r][1] : u[r][0])
                 + __shfl_xor_sync(~0u, b2 ? u[r][0] : u[r][1], 4);

        float zA = f[0] + bcj;
        float zB = f[1] + bcj;
        float eA = __expf(2.0f * zA);
        float eB = __expf(2.0f * zB);
        float hAv = 1.0f - __fdividef(2.0f, eA + 1.0f);
        float hBv = 1.0f - __fdividef(2.0f, eB + 1.0f);

        wbuf[sst] = hAv;                   // next-step state (double buffer)
        wbuf[160 + sst] = hBv;

        // rolling history (thread-private slots; no sync needed)
        int ypar = (t >> 4) & 1;
        hist[((0 * 2 + ypar) * 16 + tt) * 128 + tid] = hAv;
        hist[((2 + ypar) * 16 + tt) * 128 + tid] = hBv;

        // ---- pooling burst: grid row y = t>>4 just completed ----
        if (tt == 15) {
            int y = t >> 4;
            int oyS = (y == 0) ? 0 : 2 * y - 1;
            int oyE = (y == 0) ? 0 : ((y == 15) ? 31 : 2 * y);
            for (int oy = oyS; oy <= oyE; oy++) {
                float ysf = (float)(oy * 15) / 31.0f;
                int y0 = (int)ysf;
                float wy = ysf - (float)y0;
                int y1 = (wy > 0.0f) ? (y0 + 1) : y0;   // wy==0 -> same row (row y1 may not exist yet)
                int p0 = y0 & 1, p1 = y1 & 1;
                #pragma unroll
                for (int r = 0; r < 2; r++) {
                    const float* h0p = hist + ((r * 2 + p0) * 16) * 128 + tid;
                    const float* h1p = hist + ((r * 2 + p1) * 16) * 128 + tid;
                    float rv[16];
                    #pragma unroll
                    for (int xq = 0; xq < 16; xq++) {
                        float a = h0p[xq * 128], c = h1p[xq * 128];
                        rv[xq] = fmaf(c - a, wy, a);
                    }
                    float accl = 0.f;
                    #pragma unroll
                    for (int ox = 0; ox < 32; ox++) {
                        const int x0 = (ox * 15) / 31;
                        const int x1 = (x0 + 1 < 16) ? (x0 + 1) : 15;
                        const float wx = (float)(ox * 15) / 31.0f - (float)x0;
                        float v = fmaf(rv[x1] - rv[x0], wx, rv[x0]);
                        accl = fmaf(v, fminf(fmaxf(v + 3.0f, 0.0f), 6.0f), accl);
                    }
                    if (r == 0) accA += accl; else accB += accl;
                }
            }
        }

        __syncthreads();                   // RAW: h(t) + staged x visible
    }

    d_pooled[(size_t)r0 * 128 + j_out]       = accA * (1.0f / (6.0f * 1024.0f));
    d_pooled[(size_t)(r0 + 1) * 128 + j_out] = accB * (1.0f / (6.0f * 1024.0f));
}

// ---------------------------------------------------------------------------
// Kernel E: out[b][o] = b_out[o] + sum_j pooled[b][j] * W_out[o][j]
// 32x32 tiles, grid (16,16) = 256 CTAs, 2x2 microtile, one barrier.
// ---------------------------------------------------------------------------
__global__ void __launch_bounds__(256) out_gemm(const float* __restrict__ W_out,
                                                const float* __restrict__ b_out,
                                                float* __restrict__ out) {
    __shared__ float ws[32][129];
    __shared__ float ps[32][129];

    int tid = threadIdx.x;
    int o0 = blockIdx.x * 32, b0 = blockIdx.y * 32;

    #pragma unroll
    for (int i = 0; i < 4; i++) {
        int idx4 = i * 256 + tid;
        int r = idx4 >> 5, c4 = idx4 & 31;
        float4 w = *(const float4*)&W_out[(o0 + r) * 128 + c4 * 4];
        ws[r][c4 * 4 + 0] = w.x; ws[r][c4 * 4 + 1] = w.y;
        ws[r][c4 * 4 + 2] = w.z; ws[r][c4 * 4 + 3] = w.w;
        float4 p = *(const float4*)&d_pooled[(b0 + r) * 128 + c4 * 4];
        ps[r][c4 * 4 + 0] = p.x; ps[r][c4 * 4 + 1] = p.y;
        ps[r][c4 * 4 + 2] = p.z; ps[r][c4 * 4 + 3] = p.w;
    }
    __syncthreads();

    int to = (tid & 15) * 2;
    int tb = (tid >> 4) * 2;

    float acc[2][2] = {};
    #pragma unroll 8
    for (int k = 0; k < 128; k++) {
        float w0 = ws[to][k], w1 = ws[to + 1][k];
        float p0 = ps[tb][k], p1 = ps[tb + 1][k];
        acc[0][0] = fmaf(p0, w0, acc[0][0]);
        acc[0][1] = fmaf(p0, w1, acc[0][1]);
        acc[1][0] = fmaf(p1, w0, acc[1][0]);
        acc[1][1] = fmaf(p1, w1, acc[1][1]);
    }

    #pragma unroll
    for (int mb = 0; mb < 2; mb++)
        #pragma unroll
        for (int mo = 0; mo < 2; mo++)
            out[(b0 + tb + mb) * 512 + o0 + to + mo] = acc[mb][mo] + b_out[o0 + to + mo];
}

// ---------------------------------------------------------------------------
extern "C" void kernel_launch(void* const* d_in, const int* in_sizes, int n_in,
                              void* d_out, int out_size) {
    const float* x     = (const float*)d_in[0];
    const float* h0    = (const float*)d_in[1];
    const float* W_in  = (const float*)d_in[2];
    const float* b_in  = (const float*)d_in[3];
    const float* W_ih  = (const float*)d_in[4];
    const float* b_ih  = (const float*)d_in[5];
    const float* W_hh  = (const float*)d_in[6];
    const float* b_hh  = (const float*)d_in[7];
    const float* W_out = (const float*)d_in[8];
    const float* b_out = (const float*)d_in[9];
    float* out = (float*)d_out;

    const int RNN_SMEM = (16384 + 640 + 2048) * 4;   // hist + hsm + xsm = 84,480 B
    cudaFuncSetAttribute(rnn_kernel, cudaFuncAttributeMaxDynamicSharedMemorySize, RNN_SMEM);

    combine_kernel<<<16, 256>>>(W_in, b_in, W_ih, b_ih, b_hh);
    rnn_kernel<<<256, 128, RNN_SMEM>>>(x, h0, W_hh);
    out_gemm<<<dim3(16, 16), 256>>>(W_out, b_out, out);
}